// round 13
// baseline (speedup 1.0000x reference)
#include <cuda_runtime.h>
#include <cuda_bf16.h>
#include <stdint.h>
#include <math.h>

// ---------------- problem constants ----------------
#define DIMC      64
#define HW        256          // 16x16
#define BATCH     256
#define EMB_DIM   45184
#define OFF_CNNW  0
#define OFF_CNNB  36864
#define OFF_PROJW 36928
#define OFF_PROJB 45120
#define BHW       (BATCH*DIMC*HW)   // 16 MB

typedef unsigned long long ull_t;

// scratch
__device__ float g_h1[BHW];
__device__ float g_h2[BHW];
// projected conv-input, bf16 split hi/lo, layout [b][pos][ch]
__device__ __nv_bfloat16 g_cih[BATCH*HW*DIMC];
__device__ __nv_bfloat16 g_cil[BATCH*HW*DIMC];
// combined conv weights, per mod, tap-major, split bf16: [mod][b][tap][oc][cl]
__device__ __nv_bfloat16 g_wh[3*BATCH*9*64*64];
__device__ __nv_bfloat16 g_wl[3*BATCH*9*64*64];
// combined proj weights, split bf16: [mod][b][half][oc][k64]
__device__ __nv_bfloat16 g_pwh[3*BATCH*2*64*64];
__device__ __nv_bfloat16 g_pwl[3*BATCH*2*64*64];

__device__ __forceinline__ void softmax_n(const float* x, float* y, int n) {
    float m = x[0];
    for (int i = 1; i < n; i++) m = fmaxf(m, x[i]);
    float s = 0.f;
    for (int i = 0; i < n; i++) { y[i] = expf(x[i] - m); s += y[i]; }
    float inv = 1.f / s;
    for (int i = 0; i < n; i++) y[i] *= inv;
}

__device__ __forceinline__ uint32_t smem_to_u32(const void* p) {
    uint32_t a;
    asm("{ .reg .u64 t; cvta.to.shared.u64 t, %1; cvt.u32.u64 %0, t; }" : "=r"(a) : "l"(p));
    return a;
}

// ldmatrix x4 (sm_75+ baseline)
__device__ __forceinline__ void ldmx4(uint32_t* r, uint32_t addr) {
    asm volatile("ldmatrix.sync.aligned.m8n8.x4.shared.b16 {%0,%1,%2,%3}, [%4];"
        : "=r"(r[0]), "=r"(r[1]), "=r"(r[2]), "=r"(r[3]) : "r"(addr));
}
// bf16 HMMA (sm_80+ baseline)
__device__ __forceinline__ void mma16816(float* d, const uint32_t* a, const uint32_t* b) {
    asm volatile("mma.sync.aligned.m16n8k16.row.col.f32.bf16.bf16.f32 "
        "{%0,%1,%2,%3}, {%4,%5,%6,%7}, {%8,%9}, {%0,%1,%2,%3};"
        : "+f"(d[0]), "+f"(d[1]), "+f"(d[2]), "+f"(d[3])
        : "r"(a[0]), "r"(a[1]), "r"(a[2]), "r"(a[3]), "r"(b[0]), "r"(b[1]));
}

__device__ __forceinline__ __nv_bfloat162 split_hi2(float x, float y) {
    __nv_bfloat162 r; r.x = __float2bfloat16(x); r.y = __float2bfloat16(y); return r;
}
__device__ __forceinline__ __nv_bfloat162 split_lo2(float x, float y,
                                                    __nv_bfloat162 h) {
    __nv_bfloat162 r;
    r.x = __float2bfloat16(x - __bfloat162float(h.x));
    r.y = __float2bfloat16(y - __bfloat162float(h.y));
    return r;
}

// =====================================================================
// Kernel W: combine conv + proj weights for ALL modules, one launch.
// grid 3840 = 256 b x 3 mod x (4 conv oc-chunks + 1 proj chunk), 128 thr.
// =====================================================================
__global__ void __launch_bounds__(128)
wcomb_all_kernel(const int* __restrict__ question,
                 const float* __restrict__ emb,
                 const float* __restrict__ alpha)
{
    __shared__ float ws[16*580];
    __shared__ float s_a[3];
    const int idx   = blockIdx.x;
    const int b     = idx / 15;
    const int r     = idx % 15;
    const int mod   = r / 5;
    const int sub   = r % 5;
    const int tid   = threadIdx.x;

    if (tid == 0) {
        float tmp[3], sf[3];
        for (int t = 0; t < 3; t++) tmp[t] = alpha[mod*3 + t];
        softmax_n(tmp, sf, 3);
        s_a[0] = sf[0]; s_a[1] = sf[1]; s_a[2] = sf[2];
    }
    __syncthreads();
    const float a0 = s_a[0], a1 = s_a[1], a2 = s_a[2];
    const float* r0 = emb + (size_t)question[b*3 + 0] * EMB_DIM;
    const float* r1 = emb + (size_t)question[b*3 + 1] * EMB_DIM;
    const float* r2 = emb + (size_t)question[b*3 + 2] * EMB_DIM;

    if (sub == 4) {
        // proj weights: [half][oc][k64] bf16 split
        const size_t pbase = ((size_t)mod*BATCH + b) * 2*64*64;
        for (int i4 = tid; i4 < 2048; i4 += 128) {
            const int oc = i4 >> 5;
            const int k4 = (i4 & 31) * 4;
            const int f  = OFF_PROJW + oc*128 + k4;
            float4 x = *(const float4*)(r0 + f);
            float4 y = *(const float4*)(r1 + f);
            float4 z = *(const float4*)(r2 + f);
            float4 o;
            o.x = a0*x.x + a1*y.x + a2*z.x;
            o.y = a0*x.y + a1*y.y + a2*z.y;
            o.z = a0*x.z + a1*y.z + a2*z.z;
            o.w = a0*x.w + a1*y.w + a2*z.w;
            const int half = k4 >> 6;
            const int kk   = k4 & 63;
            __nv_bfloat162 hp0 = split_hi2(o.x, o.y);
            __nv_bfloat162 lp0 = split_lo2(o.x, o.y, hp0);
            __nv_bfloat162 hp1 = split_hi2(o.z, o.w);
            __nv_bfloat162 lp1 = split_lo2(o.z, o.w, hp1);
            const size_t gi = pbase + (size_t)half*4096 + oc*64 + kk;
            *(__nv_bfloat162*)&g_pwh[gi]     = hp0;
            *(__nv_bfloat162*)&g_pwh[gi + 2] = hp1;
            *(__nv_bfloat162*)&g_pwl[gi]     = lp0;
            *(__nv_bfloat162*)&g_pwl[gi + 2] = lp1;
        }
        return;
    }

    const int chunk = sub;
    const size_t obase = ((size_t)mod*BATCH + b) * 9 * 4096;
    const int oc0 = chunk * 16;

    for (int i4 = tid; i4 < 16*144; i4 += 128) {
        const int oc_l = i4 / 144;
        const int c4   = i4 % 144;
        const int f = (oc0 + oc_l)*576 + c4*4;
        float4 x = *(const float4*)(r0 + f);
        float4 y = *(const float4*)(r1 + f);
        float4 z = *(const float4*)(r2 + f);
        float4 o;
        o.x = a0*x.x + a1*y.x + a2*z.x;
        o.y = a0*x.y + a1*y.y + a2*z.y;
        o.z = a0*x.z + a1*y.z + a2*z.z;
        o.w = a0*x.w + a1*y.w + a2*z.w;
        *(float4*)&ws[oc_l*580 + c4*4] = o;
    }
    __syncthreads();
    for (int tap = 0; tap < 9; ++tap) {
        for (int e2 = tid; e2 < 512; e2 += 128) {
            const int oc_l = e2 >> 5;
            const int cl   = (e2 & 31) * 2;
            const float w0 = ws[oc_l*580 + cl*9 + tap];
            const float w1 = ws[oc_l*580 + (cl + 1)*9 + tap];
            __nv_bfloat162 hp = split_hi2(w0, w1);
            __nv_bfloat162 lp = split_lo2(w0, w1, hp);
            const size_t gi = obase + (size_t)tap*4096 + (oc0 + oc_l)*64 + cl;
            *(__nv_bfloat162*)&g_wh[gi] = hp;
            *(__nv_bfloat162*)&g_wl[gi] = lp;
        }
    }
}

// =====================================================================
// Kernel P (HMMA): per-batch projection via mma.sync bf16 split.
// grid 512 = 256 b x 2 pos-halves, 256 thr (8 warps), 3 CTAs/SM.
// D[128 pos, 64 ch] = inp[128,128] @ W[128,64]^T + pb; 2 K-halves.
// B = pure row copy from precomputed g_pwh/g_pwl.
// Epilogue: split to bf16 hi/lo and store g_cih/g_cil [b][pos][ch].
// =====================================================================
#define CPITCH 144
#define PJ_BH   0                         // 64*144 = 9216
#define PJ_BL   9216                      // -> 18432
#define PJ_PB   18432                     // 64 floats -> 18688
#define PJ_SC   18688                     // 9 scalars (pad 64) -> 18752
#define PJ_AH   18752                     // 128*144 = 18432 -> 37184
#define PJ_AL   37184                     // -> 55616
#define PJ_TOT  55616

__global__ void __launch_bounds__(256, 3)
projm_kernel(const int* __restrict__ question,
             const float* __restrict__ img,
             const float* __restrict__ emb,
             const float* __restrict__ alpha,
             const float* __restrict__ tau0,
             const float* __restrict__ tau1,
             int mod)
{
    extern __shared__ char smem[];
    const uint32_t sb = smem_to_u32(smem);
    const int b    = blockIdx.x >> 1;
    const int ph   = blockIdx.x & 1;      // pos half: 0 -> 0..127, 1 -> 128..255
    const int tid  = threadIdx.x;
    const int warp = tid >> 5;
    const int lane = tid & 31;
    float* s_pb   = (float*)(smem + PJ_PB);
    float* s_scal = (float*)(smem + PJ_SC);

    if (tid == 0) {
        float tmp[4], sf[4];
        for (int t = 0; t < 3; t++) tmp[t] = alpha[mod*3 + t];
        softmax_n(tmp, sf, 3);
        s_scal[0] = sf[0]; s_scal[1] = sf[1]; s_scal[2] = sf[2];
        const int n = mod + 2;
        for (int m = 0; m < n; m++) tmp[m] = tau0[mod*4 + m];
        softmax_n(tmp, sf, n);
        s_scal[3] = sf[1];
        s_scal[4] = (n > 2) ? sf[2] : 0.f;
        s_scal[5] = (n > 3) ? sf[3] : 0.f;
        for (int m = 0; m < n; m++) tmp[m] = tau1[mod*4 + m];
        softmax_n(tmp, sf, n);
        s_scal[6] = sf[1];
        s_scal[7] = (n > 2) ? sf[2] : 0.f;
        s_scal[8] = (n > 3) ? sf[3] : 0.f;
    }
    __syncthreads();

    const float a0 = s_scal[0], a1 = s_scal[1], a2 = s_scal[2];
    const float* r0 = emb + (size_t)question[b*3 + 0] * EMB_DIM;
    const float* r1 = emb + (size_t)question[b*3 + 1] * EMB_DIM;
    const float* r2 = emb + (size_t)question[b*3 + 2] * EMB_DIM;
    if (tid < 64)
        s_pb[tid] = a0*r0[OFF_PROJB + tid] + a1*r1[OFF_PROJB + tid] + a2*r2[OFF_PROJB + tid];

    // lane-dependent fragment address pieces
    const int wl   = lane & 15;
    const int kh16 = (lane >> 4) * 16;
    const int oc_l = ((lane >> 4) & 1)*8 + (lane & 7);
    const int koff = ((lane >> 3) & 1) * 16;
    const int g    = lane >> 2;
    const int tg   = lane & 3;

    const float4* img4 = (const float4*)(img  + (size_t)b * DIMC * HW);
    const float4* h14  = (const float4*)(g_h1 + (size_t)b * DIMC * HW);
    const float4* h24  = (const float4*)(g_h2 + (size_t)b * DIMC * HW);
    const char* pwh = (const char*)(g_pwh + ((size_t)mod*BATCH + b) * 2*64*64);
    const char* pwl = (const char*)(g_pwl + ((size_t)mod*BATCH + b) * 2*64*64);

    // accumulators init with proj bias (col = n*8 + 2tg {,+1})
    float d[8][4];
    __syncthreads();   // s_pb ready
    #pragma unroll
    for (int n = 0; n < 8; n++) {
        const float p0 = s_pb[n*8 + 2*tg];
        const float p1 = s_pb[n*8 + 2*tg + 1];
        d[n][0] = p0; d[n][1] = p1;
        d[n][2] = p0; d[n][3] = p1;
    }

    for (int half = 0; half < 2; ++half) {
        const float w1 = s_scal[3 + 3*half + 0];
        const float w2 = s_scal[3 + 3*half + 1];
        const float w3 = s_scal[3 + 3*half + 2];
        __syncthreads();   // prev half's smem reads done

        // A stage: inp-half [128 pos][64 ch] bf16 hi/lo, pitch 144
        for (int ii = tid; ii < 1024; ii += 256) {
            const int cp = ii >> 5;              // channel pair 0..31
            const int q  = ii & 31;              // local pos4 group 0..31
            const int i0 = (2*cp)*64 + ph*32 + q;
            float4 u0 = img4[i0];
            float4 u1 = img4[i0 + 64];
            float4 o0, o1;
            o0.x = w1*u0.x; o0.y = w1*u0.y; o0.z = w1*u0.z; o0.w = w1*u0.w;
            o1.x = w1*u1.x; o1.y = w1*u1.y; o1.z = w1*u1.z; o1.w = w1*u1.w;
            if (mod >= 1) {
                float4 v0 = h14[i0], v1 = h14[i0 + 64];
                o0.x += w2*v0.x; o0.y += w2*v0.y; o0.z += w2*v0.z; o0.w += w2*v0.w;
                o1.x += w2*v1.x; o1.y += w2*v1.y; o1.z += w2*v1.z; o1.w += w2*v1.w;
            }
            if (mod >= 2) {
                float4 v0 = h24[i0], v1 = h24[i0 + 64];
                o0.x += w3*v0.x; o0.y += w3*v0.y; o0.z += w3*v0.z; o0.w += w3*v0.w;
                o1.x += w3*v1.x; o1.y += w3*v1.y; o1.z += w3*v1.z; o1.w += w3*v1.w;
            }
            const float x0[4] = { o0.x, o0.y, o0.z, o0.w };
            const float x1[4] = { o1.x, o1.y, o1.z, o1.w };
            const int p0 = q * 4;                // local pos base
            #pragma unroll
            for (int l = 0; l < 4; l++) {
                __nv_bfloat162 hp = split_hi2(x0[l], x1[l]);
                __nv_bfloat162 lp = split_lo2(x0[l], x1[l], hp);
                *(__nv_bfloat162*)(smem + PJ_AH + (p0 + l)*CPITCH + cp*4) = hp;
                *(__nv_bfloat162*)(smem + PJ_AL + (p0 + l)*CPITCH + cp*4) = lp;
            }
        }
        // B stage: pure 128B row copy from precomputed weights
        for (int i = tid; i < 512; i += 256) {
            const int oc = i >> 3;
            const int q  = i & 7;
            *(float4*)(smem + PJ_BH + oc*CPITCH + q*16) =
                *(const float4*)(pwh + (size_t)half*8192 + oc*128 + q*16);
            *(float4*)(smem + PJ_BL + oc*CPITCH + q*16) =
                *(const float4*)(pwl + (size_t)half*8192 + oc*128 + q*16);
        }
        __syncthreads();

        #pragma unroll
        for (int k16 = 0; k16 < 4; ++k16) {
            const int kb = k16 * 32;
            uint32_t ah[4], al[4];
            const uint32_t apix = (uint32_t)((warp*16 + wl)*CPITCH + kh16 + kb);
            ldmx4(ah, sb + PJ_AH + apix);
            ldmx4(al, sb + PJ_AL + apix);
            #pragma unroll
            for (int nt2 = 0; nt2 < 4; ++nt2) {
                uint32_t bh[4], bl[4];
                const uint32_t boff = (uint32_t)((nt2*16 + oc_l)*CPITCH + kb + koff);
                ldmx4(bh, sb + PJ_BH + boff);
                ldmx4(bl, sb + PJ_BL + boff);
                mma16816(d[2*nt2],     ah, bh);
                mma16816(d[2*nt2],     al, bh);
                mma16816(d[2*nt2],     ah, bl);
                mma16816(d[2*nt2 + 1], ah, bh + 2);
                mma16816(d[2*nt2 + 1], al, bh + 2);
                mma16816(d[2*nt2 + 1], ah, bl + 2);
            }
        }
    }

    // epilogue: split to bf16 hi/lo -> g_cih/g_cil [b][pos][ch]
    __nv_bfloat16* cih = g_cih + (size_t)b * HW * DIMC;
    __nv_bfloat16* cil = g_cil + (size_t)b * HW * DIMC;
    const int row0 = ph*128 + warp*16 + g;
    #pragma unroll
    for (int n = 0; n < 8; n++) {
        const int col = n*8 + 2*tg;
        __nv_bfloat162 h0 = split_hi2(d[n][0], d[n][1]);
        __nv_bfloat162 l0 = split_lo2(d[n][0], d[n][1], h0);
        __nv_bfloat162 h1 = split_hi2(d[n][2], d[n][3]);
        __nv_bfloat162 l1 = split_lo2(d[n][2], d[n][3], h1);
        *(__nv_bfloat162*)(cih + row0*64 + col)       = h0;
        *(__nv_bfloat162*)(cil + row0*64 + col)       = l0;
        *(__nv_bfloat162*)(cih + (row0 + 8)*64 + col) = h1;
        *(__nv_bfloat162*)(cil + (row0 + 8)*64 + col) = l1;
    }
}

// =====================================================================
// Kernel C (HMMA): per-batch 3x3 conv via mma.sync.m16n8k16.bf16 split.
// grid 256 (1 CTA/batch), 256 thr (8 warps), 2 CTAs/SM. (unchanged)
// =====================================================================
#define DPITCH 1072                       // 268 floats, 16B-aligned
#define SMB_H   0                         // 64*144 = 9216
#define SMB_L   9216
#define SM_BIAS 18432                     // 64 floats
#define SM_SCAL 18688                     // 3 floats (pad 16)
#define SM_CI_H 18704                     // 324 pixels * 144 = 46656
#define SM_CI_L (SM_CI_H + 46656)
#define SM_TOT  (SM_CI_L + 46656)         // 112016
#define SM_DST  SM_CI_H                   // reuse: 64*1072 = 68608 <= 93312

__global__ void __launch_bounds__(256, 2)
convm_kernel(const int* __restrict__ question,
             const float* __restrict__ emb,
             const float* __restrict__ alpha,
             float* __restrict__ out_final,
             int mod)
{
    extern __shared__ char smem[];
    const uint32_t sb = smem_to_u32(smem);
    const int b    = blockIdx.x;
    const int tid  = threadIdx.x;
    const int warp = tid >> 5;
    const int lane = tid & 31;
    float* s_scal = (float*)(smem + SM_SCAL);
    float* s_bias = (float*)(smem + SM_BIAS);

    if (tid == 0) {
        float tmp[3], sf[3];
        for (int t = 0; t < 3; t++) tmp[t] = alpha[mod*3 + t];
        softmax_n(tmp, sf, 3);
        s_scal[0] = sf[0]; s_scal[1] = sf[1]; s_scal[2] = sf[2];
    }
    // zero both ci stages (halo stays zero; pads unread by ldmatrix)
    {
        float4 z4 = make_float4(0.f, 0.f, 0.f, 0.f);
        float4* zp = (float4*)(smem + SM_CI_H);
        for (int i = tid; i < (2*46656)/16; i += 256) zp[i] = z4;
    }
    __syncthreads();

    const float a0 = s_scal[0], a1 = s_scal[1], a2 = s_scal[2];
    const float* r0 = emb + (size_t)question[b*3 + 0] * EMB_DIM;
    const float* r1 = emb + (size_t)question[b*3 + 1] * EMB_DIM;
    const float* r2 = emb + (size_t)question[b*3 + 2] * EMB_DIM;
    if (tid < 64)
        s_bias[tid] = a0*r0[OFF_CNNB + tid] + a1*r1[OFF_CNNB + tid] + a2*r2[OFF_CNNB + tid];

    // fill ci interior: pure 128B row copies from pre-split gmem
    {
        const char* cih = (const char*)(g_cih + (size_t)b * HW * DIMC);
        const char* cil = (const char*)(g_cil + (size_t)b * HW * DIMC);
        for (int i = tid; i < 2048; i += 256) {
            const int pos = i >> 3;
            const int q   = (i & 7) * 16;
            const int h   = pos >> 4;
            const int w   = pos & 15;
            const int pix = (h + 1)*18 + (w + 1);
            *(float4*)(smem + SM_CI_H + pix*CPITCH + q) = *(const float4*)(cih + pos*128 + q);
            *(float4*)(smem + SM_CI_L + pix*CPITCH + q) = *(const float4*)(cil + pos*128 + q);
        }
    }

    // accumulators: [m-tile][n-tile][frag]
    float d[2][8][4];
    #pragma unroll
    for (int m = 0; m < 2; m++)
        #pragma unroll
        for (int n = 0; n < 8; n++)
            #pragma unroll
            for (int q = 0; q < 4; q++) d[m][n][q] = 0.f;

    // lane-dependent ldmatrix address pieces
    const int wl    = lane & 15;
    const int kh16  = (lane >> 4) * 16;
    const int oc_l  = ((lane >> 4) & 1)*8 + (lane & 7);
    const int koff  = ((lane >> 3) & 1) * 16;
    const int h0_   = warp*2;

    const char* wsrcH = (const char*)(g_wh + ((size_t)mod*BATCH + b)*9*4096);
    const char* wsrcL = (const char*)(g_wl + ((size_t)mod*BATCH + b)*9*4096);

    for (int tap = 0; tap < 9; ++tap) {
        const int dy = tap / 3;
        const int dx = tap % 3;
        __syncthreads();     // prev-tap B reads done (and first iter: ci ready)
        for (int i = tid; i < 512; i += 256) {
            const int oc = i >> 3;
            const int q  = i & 7;
            *(float4*)(smem + SMB_H + oc*CPITCH + q*16) =
                *(const float4*)(wsrcH + (size_t)tap*8192 + oc*128 + q*16);
            *(float4*)(smem + SMB_L + oc*CPITCH + q*16) =
                *(const float4*)(wsrcL + (size_t)tap*8192 + oc*128 + q*16);
        }
        __syncthreads();

        #pragma unroll
        for (int k16 = 0; k16 < 4; ++k16) {
            const int kb = k16 * 32;
            uint32_t ah[2][4], al[2][4];
            #pragma unroll
            for (int m = 0; m < 2; m++) {
                const uint32_t apix = (uint32_t)(((h0_ + m + dy)*18 + wl + dx)*CPITCH + kh16 + kb);
                ldmx4(ah[m], sb + SM_CI_H + apix);
                ldmx4(al[m], sb + SM_CI_L + apix);
            }
            #pragma unroll
            for (int nt2 = 0; nt2 < 4; ++nt2) {
                uint32_t bh[4], bl[4];
                const uint32_t boff = (uint32_t)((nt2*16 + oc_l)*CPITCH + kb + koff);
                ldmx4(bh, sb + SMB_H + boff);
                ldmx4(bl, sb + SMB_L + boff);
                #pragma unroll
                for (int m = 0; m < 2; m++) {
                    mma16816(d[m][2*nt2],     ah[m], bh);
                    mma16816(d[m][2*nt2],     al[m], bh);
                    mma16816(d[m][2*nt2],     ah[m], bl);
                    mma16816(d[m][2*nt2 + 1], ah[m], bh + 2);
                    mma16816(d[m][2*nt2 + 1], al[m], bh + 2);
                    mma16816(d[m][2*nt2 + 1], ah[m], bl + 2);
                }
            }
        }
    }
    __syncthreads();   // all smem reads done; reuse ci region as D stage

    // scatter D frags to smem [oc][pos] pitch 1072
    {
        const int g  = lane >> 2;
        const int tg = lane & 3;
        #pragma unroll
        for (int m = 0; m < 2; m++) {
            const int hh = h0_ + m;
            const int pos0 = hh*16 + g;
            const int pos1 = pos0 + 8;
            #pragma unroll
            for (int n = 0; n < 8; n++) {
                char* base = smem + SM_DST + (n*8 + 2*tg)*DPITCH;
                *(float*)(base + pos0*4)          = d[m][n][0];
                *(float*)(base + DPITCH + pos0*4) = d[m][n][1];
                *(float*)(base + pos1*4)          = d[m][n][2];
                *(float*)(base + DPITCH + pos1*4) = d[m][n][3];
            }
        }
    }
    __syncthreads();

    float* dst = (mod == 0) ? g_h1 : (mod == 1) ? g_h2 : out_final;
    dst += (size_t)b * DIMC * HW;
    for (int i = tid; i < 4096; i += 256) {
        const int oc = i >> 6;
        const int p4 = (i & 63) * 4;
        float4 v = *(const float4*)(smem + SM_DST + oc*DPITCH + p4*4);
        const float bb = s_bias[oc];
        v.x = fmaxf(v.x + bb, 0.f);
        v.y = fmaxf(v.y + bb, 0.f);
        v.z = fmaxf(v.z + bb, 0.f);
        v.w = fmaxf(v.w + bb, 0.f);
        *(float4*)(dst + oc*256 + p4) = v;
    }
}

// =====================================================================
extern "C" void kernel_launch(void* const* d_in, const int* in_sizes, int n_in,
                              void* d_out, int out_size)
{
    const int*   question = (const int*)  d_in[0];
    const float* img      = (const float*)d_in[1];
    const float* emb      = (const float*)d_in[2];
    const float* alpha    = (const float*)d_in[3];
    const float* tau0     = (const float*)d_in[4];
    const float* tau1     = (const float*)d_in[5];
    float* out = (float*)d_out;

    cudaFuncSetAttribute(projm_kernel, cudaFuncAttributeMaxDynamicSharedMemorySize, PJ_TOT);
    cudaFuncSetAttribute(convm_kernel, cudaFuncAttributeMaxDynamicSharedMemorySize, SM_TOT);

    // all modules' conv + proj weights in one parallel launch
    wcomb_all_kernel<<<BATCH*15, 128>>>(question, emb, alpha);

    for (int mod = 0; mod < 3; ++mod) {
        projm_kernel<<<BATCH*2, 256, PJ_TOT>>>(question, img, emb, alpha, tau0, tau1, mod);
        convm_kernel<<<BATCH, 256, SM_TOT>>>(question, emb, alpha, out, mod);
    }
    (void)in_sizes; (void)n_in; (void)out_size;
}

// round 14
// speedup vs baseline: 1.0704x; 1.0704x over previous
#include <cuda_runtime.h>
#include <cuda_bf16.h>
#include <stdint.h>
#include <math.h>

// ---------------- problem constants ----------------
#define DIMC      64
#define HW        256          // 16x16
#define BATCH     256
#define EMB_DIM   45184
#define OFF_CNNW  0
#define OFF_CNNB  36864
#define OFF_PROJW 36928
#define OFF_PROJB 45120
#define BHW       (BATCH*DIMC*HW)   // 16 MB

typedef unsigned long long ull_t;

// scratch
__device__ float g_h1[BHW];
__device__ float g_h2[BHW];
// projected conv-input, bf16 split hi/lo, layout [b][pos][ch]
__device__ __nv_bfloat16 g_cih[BATCH*HW*DIMC];
__device__ __nv_bfloat16 g_cil[BATCH*HW*DIMC];
// combined conv weights, per mod, tap-major, split bf16: [mod][b][tap][oc][cl]
__device__ __nv_bfloat16 g_wh[3*BATCH*9*64*64];
__device__ __nv_bfloat16 g_wl[3*BATCH*9*64*64];
// combined proj weights, split bf16: [mod][b][half][oc][k64]
__device__ __nv_bfloat16 g_pwh[3*BATCH*2*64*64];
__device__ __nv_bfloat16 g_pwl[3*BATCH*2*64*64];

__device__ __forceinline__ void softmax_n(const float* x, float* y, int n) {
    float m = x[0];
    for (int i = 1; i < n; i++) m = fmaxf(m, x[i]);
    float s = 0.f;
    for (int i = 0; i < n; i++) { y[i] = expf(x[i] - m); s += y[i]; }
    float inv = 1.f / s;
    for (int i = 0; i < n; i++) y[i] *= inv;
}

__device__ __forceinline__ uint32_t smem_to_u32(const void* p) {
    uint32_t a;
    asm("{ .reg .u64 t; cvta.to.shared.u64 t, %1; cvt.u32.u64 %0, t; }" : "=r"(a) : "l"(p));
    return a;
}

// ldmatrix x4 (sm_75+ baseline)
__device__ __forceinline__ void ldmx4(uint32_t* r, uint32_t addr) {
    asm volatile("ldmatrix.sync.aligned.m8n8.x4.shared.b16 {%0,%1,%2,%3}, [%4];"
        : "=r"(r[0]), "=r"(r[1]), "=r"(r[2]), "=r"(r[3]) : "r"(addr));
}
// bf16 HMMA (sm_80+ baseline)
__device__ __forceinline__ void mma16816(float* d, const uint32_t* a, const uint32_t* b) {
    asm volatile("mma.sync.aligned.m16n8k16.row.col.f32.bf16.bf16.f32 "
        "{%0,%1,%2,%3}, {%4,%5,%6,%7}, {%8,%9}, {%0,%1,%2,%3};"
        : "+f"(d[0]), "+f"(d[1]), "+f"(d[2]), "+f"(d[3])
        : "r"(a[0]), "r"(a[1]), "r"(a[2]), "r"(a[3]), "r"(b[0]), "r"(b[1]));
}

__device__ __forceinline__ __nv_bfloat162 split_hi2(float x, float y) {
    __nv_bfloat162 r; r.x = __float2bfloat16(x); r.y = __float2bfloat16(y); return r;
}
__device__ __forceinline__ __nv_bfloat162 split_lo2(float x, float y,
                                                    __nv_bfloat162 h) {
    __nv_bfloat162 r;
    r.x = __float2bfloat16(x - __bfloat162float(h.x));
    r.y = __float2bfloat16(y - __bfloat162float(h.y));
    return r;
}

// =====================================================================
// Kernel W: combine conv + proj weights for ALL modules, one launch.
// grid 3840 = 256 b x 3 mod x (4 conv oc-chunks + 1 proj chunk), 128 thr.
// =====================================================================
__global__ void __launch_bounds__(128)
wcomb_all_kernel(const int* __restrict__ question,
                 const float* __restrict__ emb,
                 const float* __restrict__ alpha)
{
    __shared__ float ws[16*580];
    __shared__ float s_a[3];
    const int idx   = blockIdx.x;
    const int b     = idx / 15;
    const int r     = idx % 15;
    const int mod   = r / 5;
    const int sub   = r % 5;
    const int tid   = threadIdx.x;

    if (tid == 0) {
        float tmp[3], sf[3];
        for (int t = 0; t < 3; t++) tmp[t] = alpha[mod*3 + t];
        softmax_n(tmp, sf, 3);
        s_a[0] = sf[0]; s_a[1] = sf[1]; s_a[2] = sf[2];
    }
    __syncthreads();
    const float a0 = s_a[0], a1 = s_a[1], a2 = s_a[2];
    const float* r0 = emb + (size_t)question[b*3 + 0] * EMB_DIM;
    const float* r1 = emb + (size_t)question[b*3 + 1] * EMB_DIM;
    const float* r2 = emb + (size_t)question[b*3 + 2] * EMB_DIM;

    if (sub == 4) {
        // proj weights: [half][oc][k64] bf16 split
        const size_t pbase = ((size_t)mod*BATCH + b) * 2*64*64;
        for (int i4 = tid; i4 < 2048; i4 += 128) {
            const int oc = i4 >> 5;
            const int k4 = (i4 & 31) * 4;
            const int f  = OFF_PROJW + oc*128 + k4;
            float4 x = *(const float4*)(r0 + f);
            float4 y = *(const float4*)(r1 + f);
            float4 z = *(const float4*)(r2 + f);
            float4 o;
            o.x = a0*x.x + a1*y.x + a2*z.x;
            o.y = a0*x.y + a1*y.y + a2*z.y;
            o.z = a0*x.z + a1*y.z + a2*z.z;
            o.w = a0*x.w + a1*y.w + a2*z.w;
            const int half = k4 >> 6;
            const int kk   = k4 & 63;
            __nv_bfloat162 hp0 = split_hi2(o.x, o.y);
            __nv_bfloat162 lp0 = split_lo2(o.x, o.y, hp0);
            __nv_bfloat162 hp1 = split_hi2(o.z, o.w);
            __nv_bfloat162 lp1 = split_lo2(o.z, o.w, hp1);
            const size_t gi = pbase + (size_t)half*4096 + oc*64 + kk;
            *(__nv_bfloat162*)&g_pwh[gi]     = hp0;
            *(__nv_bfloat162*)&g_pwh[gi + 2] = hp1;
            *(__nv_bfloat162*)&g_pwl[gi]     = lp0;
            *(__nv_bfloat162*)&g_pwl[gi + 2] = lp1;
        }
        return;
    }

    const int chunk = sub;
    const size_t obase = ((size_t)mod*BATCH + b) * 9 * 4096;
    const int oc0 = chunk * 16;

    for (int i4 = tid; i4 < 16*144; i4 += 128) {
        const int oc_l = i4 / 144;
        const int c4   = i4 % 144;
        const int f = (oc0 + oc_l)*576 + c4*4;
        float4 x = *(const float4*)(r0 + f);
        float4 y = *(const float4*)(r1 + f);
        float4 z = *(const float4*)(r2 + f);
        float4 o;
        o.x = a0*x.x + a1*y.x + a2*z.x;
        o.y = a0*x.y + a1*y.y + a2*z.y;
        o.z = a0*x.z + a1*y.z + a2*z.z;
        o.w = a0*x.w + a1*y.w + a2*z.w;
        *(float4*)&ws[oc_l*580 + c4*4] = o;
    }
    __syncthreads();
    for (int tap = 0; tap < 9; ++tap) {
        for (int e2 = tid; e2 < 512; e2 += 128) {
            const int oc_l = e2 >> 5;
            const int cl   = (e2 & 31) * 2;
            const float w0 = ws[oc_l*580 + cl*9 + tap];
            const float w1 = ws[oc_l*580 + (cl + 1)*9 + tap];
            __nv_bfloat162 hp = split_hi2(w0, w1);
            __nv_bfloat162 lp = split_lo2(w0, w1, hp);
            const size_t gi = obase + (size_t)tap*4096 + (oc0 + oc_l)*64 + cl;
            *(__nv_bfloat162*)&g_wh[gi] = hp;
            *(__nv_bfloat162*)&g_wl[gi] = lp;
        }
    }
}

// =====================================================================
// Kernel P (HMMA): per-batch projection via mma.sync bf16 split.
// grid 256 (1 CTA/batch), 256 thr (8 warps), 2 CTAs/SM.
// D[256 pos, 64 ch] = inp[256,128] @ W[128,64]^T + pb; 2 K-halves.
// B = pure 128B row copy from precomputed g_pwh/g_pwl (no gather).
// Epilogue: split to bf16 hi/lo and store g_cih/g_cil [b][pos][ch].
// =====================================================================
#define CPITCH 144
#define PJ_BH   0                         // 64*144 = 9216
#define PJ_BL   9216                      // -> 18432
#define PJ_PB   18432                     // 64 floats -> 18688
#define PJ_SC   18688                     // 9 scalars (pad 64) -> 18752
#define PJ_AH   18752                     // 256*144 = 36864 -> 55616
#define PJ_AL   55616                     // -> 92480
#define PJ_TOT  92480

__global__ void __launch_bounds__(256, 2)
projm_kernel(const int* __restrict__ question,
             const float* __restrict__ img,
             const float* __restrict__ emb,
             const float* __restrict__ alpha,
             const float* __restrict__ tau0,
             const float* __restrict__ tau1,
             int mod)
{
    extern __shared__ char smem[];
    const uint32_t sb = smem_to_u32(smem);
    const int b    = blockIdx.x;
    const int tid  = threadIdx.x;
    const int warp = tid >> 5;
    const int lane = tid & 31;
    float* s_pb   = (float*)(smem + PJ_PB);
    float* s_scal = (float*)(smem + PJ_SC);

    if (tid == 0) {
        float tmp[4], sf[4];
        for (int t = 0; t < 3; t++) tmp[t] = alpha[mod*3 + t];
        softmax_n(tmp, sf, 3);
        s_scal[0] = sf[0]; s_scal[1] = sf[1]; s_scal[2] = sf[2];
        const int n = mod + 2;
        for (int m = 0; m < n; m++) tmp[m] = tau0[mod*4 + m];
        softmax_n(tmp, sf, n);
        s_scal[3] = sf[1];
        s_scal[4] = (n > 2) ? sf[2] : 0.f;
        s_scal[5] = (n > 3) ? sf[3] : 0.f;
        for (int m = 0; m < n; m++) tmp[m] = tau1[mod*4 + m];
        softmax_n(tmp, sf, n);
        s_scal[6] = sf[1];
        s_scal[7] = (n > 2) ? sf[2] : 0.f;
        s_scal[8] = (n > 3) ? sf[3] : 0.f;
    }
    __syncthreads();

    const float a0 = s_scal[0], a1 = s_scal[1], a2 = s_scal[2];
    const float* r0 = emb + (size_t)question[b*3 + 0] * EMB_DIM;
    const float* r1 = emb + (size_t)question[b*3 + 1] * EMB_DIM;
    const float* r2 = emb + (size_t)question[b*3 + 2] * EMB_DIM;
    if (tid < 64)
        s_pb[tid] = a0*r0[OFF_PROJB + tid] + a1*r1[OFF_PROJB + tid] + a2*r2[OFF_PROJB + tid];

    // lane-dependent fragment address pieces
    const int wl   = lane & 15;
    const int kh16 = (lane >> 4) * 16;
    const int oc_l = ((lane >> 4) & 1)*8 + (lane & 7);
    const int koff = ((lane >> 3) & 1) * 16;
    const int g    = lane >> 2;
    const int tg   = lane & 3;

    const float4* img4 = (const float4*)(img  + (size_t)b * DIMC * HW);
    const float4* h14  = (const float4*)(g_h1 + (size_t)b * DIMC * HW);
    const float4* h24  = (const float4*)(g_h2 + (size_t)b * DIMC * HW);
    const char* pwh = (const char*)(g_pwh + ((size_t)mod*BATCH + b) * 2*64*64);
    const char* pwl = (const char*)(g_pwl + ((size_t)mod*BATCH + b) * 2*64*64);

    // accumulators init with proj bias (col = n*8 + 2tg {,+1})
    float d[2][8][4];
    __syncthreads();   // s_pb ready
    #pragma unroll
    for (int n = 0; n < 8; n++) {
        const float p0 = s_pb[n*8 + 2*tg];
        const float p1 = s_pb[n*8 + 2*tg + 1];
        #pragma unroll
        for (int m = 0; m < 2; m++) {
            d[m][n][0] = p0; d[m][n][1] = p1;
            d[m][n][2] = p0; d[m][n][3] = p1;
        }
    }

    for (int half = 0; half < 2; ++half) {
        const float w1 = s_scal[3 + 3*half + 0];
        const float w2 = s_scal[3 + 3*half + 1];
        const float w3 = s_scal[3 + 3*half + 2];
        __syncthreads();   // prev half's smem reads done

        // A stage: inp-half [pos 256][ch 64] bf16 hi/lo, pitch 144
        for (int ii = tid; ii < 2048; ii += 256) {
            const int cp = ii >> 6;              // channel pair 0..31
            const int q  = ii & 63;              // pos4 group
            const int i0 = (2*cp)*64 + q;
            float4 u0 = img4[i0];
            float4 u1 = img4[i0 + 64];
            float4 o0, o1;
            o0.x = w1*u0.x; o0.y = w1*u0.y; o0.z = w1*u0.z; o0.w = w1*u0.w;
            o1.x = w1*u1.x; o1.y = w1*u1.y; o1.z = w1*u1.z; o1.w = w1*u1.w;
            if (mod >= 1) {
                float4 v0 = h14[i0], v1 = h14[i0 + 64];
                o0.x += w2*v0.x; o0.y += w2*v0.y; o0.z += w2*v0.z; o0.w += w2*v0.w;
                o1.x += w2*v1.x; o1.y += w2*v1.y; o1.z += w2*v1.z; o1.w += w2*v1.w;
            }
            if (mod >= 2) {
                float4 v0 = h24[i0], v1 = h24[i0 + 64];
                o0.x += w3*v0.x; o0.y += w3*v0.y; o0.z += w3*v0.z; o0.w += w3*v0.w;
                o1.x += w3*v1.x; o1.y += w3*v1.y; o1.z += w3*v1.z; o1.w += w3*v1.w;
            }
            const float x0[4] = { o0.x, o0.y, o0.z, o0.w };
            const float x1[4] = { o1.x, o1.y, o1.z, o1.w };
            const int p0 = q * 4;
            #pragma unroll
            for (int l = 0; l < 4; l++) {
                __nv_bfloat162 hp = split_hi2(x0[l], x1[l]);
                __nv_bfloat162 lp = split_lo2(x0[l], x1[l], hp);
                *(__nv_bfloat162*)(smem + PJ_AH + (p0 + l)*CPITCH + cp*4) = hp;
                *(__nv_bfloat162*)(smem + PJ_AL + (p0 + l)*CPITCH + cp*4) = lp;
            }
        }
        // B stage: pure 128B row copy from precomputed weights
        for (int i = tid; i < 512; i += 256) {
            const int oc = i >> 3;
            const int q  = i & 7;
            *(float4*)(smem + PJ_BH + oc*CPITCH + q*16) =
                *(const float4*)(pwh + (size_t)half*8192 + oc*128 + q*16);
            *(float4*)(smem + PJ_BL + oc*CPITCH + q*16) =
                *(const float4*)(pwl + (size_t)half*8192 + oc*128 + q*16);
        }
        __syncthreads();

        #pragma unroll
        for (int k16 = 0; k16 < 4; ++k16) {
            const int kb = k16 * 32;
            uint32_t ah[2][4], al[2][4];
            #pragma unroll
            for (int m = 0; m < 2; m++) {
                const uint32_t apix = (uint32_t)((warp*32 + m*16 + wl)*CPITCH + kh16 + kb);
                ldmx4(ah[m], sb + PJ_AH + apix);
                ldmx4(al[m], sb + PJ_AL + apix);
            }
            #pragma unroll
            for (int nt2 = 0; nt2 < 4; ++nt2) {
                uint32_t bh[4], bl[4];
                const uint32_t boff = (uint32_t)((nt2*16 + oc_l)*CPITCH + kb + koff);
                ldmx4(bh, sb + PJ_BH + boff);
                ldmx4(bl, sb + PJ_BL + boff);
                #pragma unroll
                for (int m = 0; m < 2; m++) {
                    mma16816(d[m][2*nt2],     ah[m], bh);
                    mma16816(d[m][2*nt2],     al[m], bh);
                    mma16816(d[m][2*nt2],     ah[m], bl);
                    mma16816(d[m][2*nt2 + 1], ah[m], bh + 2);
                    mma16816(d[m][2*nt2 + 1], al[m], bh + 2);
                    mma16816(d[m][2*nt2 + 1], ah[m], bl + 2);
                }
            }
        }
    }

    // epilogue: split to bf16 hi/lo -> g_cih/g_cil [b][pos][ch]
    __nv_bfloat16* cih = g_cih + (size_t)b * HW * DIMC;
    __nv_bfloat16* cil = g_cil + (size_t)b * HW * DIMC;
    #pragma unroll
    for (int m = 0; m < 2; m++) {
        const int row0 = warp*32 + m*16 + g;
        #pragma unroll
        for (int n = 0; n < 8; n++) {
            const int col = n*8 + 2*tg;
            __nv_bfloat162 h0 = split_hi2(d[m][n][0], d[m][n][1]);
            __nv_bfloat162 l0 = split_lo2(d[m][n][0], d[m][n][1], h0);
            __nv_bfloat162 h1 = split_hi2(d[m][n][2], d[m][n][3]);
            __nv_bfloat162 l1 = split_lo2(d[m][n][2], d[m][n][3], h1);
            *(__nv_bfloat162*)(cih + row0*64 + col)       = h0;
            *(__nv_bfloat162*)(cil + row0*64 + col)       = l0;
            *(__nv_bfloat162*)(cih + (row0 + 8)*64 + col) = h1;
            *(__nv_bfloat162*)(cil + (row0 + 8)*64 + col) = l1;
        }
    }
}

// =====================================================================
// Kernel C (HMMA): per-batch 3x3 conv via mma.sync.m16n8k16.bf16 split.
// grid 256 (1 CTA/batch), 256 thr (8 warps), 2 CTAs/SM. (unchanged)
// =====================================================================
#define DPITCH 1072                       // 268 floats, 16B-aligned
#define SMB_H   0                         // 64*144 = 9216
#define SMB_L   9216
#define SM_BIAS 18432                     // 64 floats
#define SM_SCAL 18688                     // 3 floats (pad 16)
#define SM_CI_H 18704                     // 324 pixels * 144 = 46656
#define SM_CI_L (SM_CI_H + 46656)
#define SM_TOT  (SM_CI_L + 46656)         // 112016
#define SM_DST  SM_CI_H                   // reuse: 64*1072 = 68608 <= 93312

__global__ void __launch_bounds__(256, 2)
convm_kernel(const int* __restrict__ question,
             const float* __restrict__ emb,
             const float* __restrict__ alpha,
             float* __restrict__ out_final,
             int mod)
{
    extern __shared__ char smem[];
    const uint32_t sb = smem_to_u32(smem);
    const int b    = blockIdx.x;
    const int tid  = threadIdx.x;
    const int warp = tid >> 5;
    const int lane = tid & 31;
    float* s_scal = (float*)(smem + SM_SCAL);
    float* s_bias = (float*)(smem + SM_BIAS);

    if (tid == 0) {
        float tmp[3], sf[3];
        for (int t = 0; t < 3; t++) tmp[t] = alpha[mod*3 + t];
        softmax_n(tmp, sf, 3);
        s_scal[0] = sf[0]; s_scal[1] = sf[1]; s_scal[2] = sf[2];
    }
    // zero both ci stages (halo stays zero; pads unread by ldmatrix)
    {
        float4 z4 = make_float4(0.f, 0.f, 0.f, 0.f);
        float4* zp = (float4*)(smem + SM_CI_H);
        for (int i = tid; i < (2*46656)/16; i += 256) zp[i] = z4;
    }
    __syncthreads();

    const float a0 = s_scal[0], a1 = s_scal[1], a2 = s_scal[2];
    const float* r0 = emb + (size_t)question[b*3 + 0] * EMB_DIM;
    const float* r1 = emb + (size_t)question[b*3 + 1] * EMB_DIM;
    const float* r2 = emb + (size_t)question[b*3 + 2] * EMB_DIM;
    if (tid < 64)
        s_bias[tid] = a0*r0[OFF_CNNB + tid] + a1*r1[OFF_CNNB + tid] + a2*r2[OFF_CNNB + tid];

    // fill ci interior: pure 128B row copies from pre-split gmem
    {
        const char* cih = (const char*)(g_cih + (size_t)b * HW * DIMC);
        const char* cil = (const char*)(g_cil + (size_t)b * HW * DIMC);
        for (int i = tid; i < 2048; i += 256) {
            const int pos = i >> 3;
            const int q   = (i & 7) * 16;
            const int h   = pos >> 4;
            const int w   = pos & 15;
            const int pix = (h + 1)*18 + (w + 1);
            *(float4*)(smem + SM_CI_H + pix*CPITCH + q) = *(const float4*)(cih + pos*128 + q);
            *(float4*)(smem + SM_CI_L + pix*CPITCH + q) = *(const float4*)(cil + pos*128 + q);
        }
    }

    // accumulators: [m-tile][n-tile][frag]
    float d[2][8][4];
    #pragma unroll
    for (int m = 0; m < 2; m++)
        #pragma unroll
        for (int n = 0; n < 8; n++)
            #pragma unroll
            for (int q = 0; q < 4; q++) d[m][n][q] = 0.f;

    // lane-dependent ldmatrix address pieces
    const int wl    = lane & 15;
    const int kh16  = (lane >> 4) * 16;
    const int oc_l  = ((lane >> 4) & 1)*8 + (lane & 7);
    const int koff  = ((lane >> 3) & 1) * 16;
    const int h0_   = warp*2;

    const char* wsrcH = (const char*)(g_wh + ((size_t)mod*BATCH + b)*9*4096);
    const char* wsrcL = (const char*)(g_wl + ((size_t)mod*BATCH + b)*9*4096);

    for (int tap = 0; tap < 9; ++tap) {
        const int dy = tap / 3;
        const int dx = tap % 3;
        __syncthreads();     // prev-tap B reads done (and first iter: ci ready)
        for (int i = tid; i < 512; i += 256) {
            const int oc = i >> 3;
            const int q  = i & 7;
            *(float4*)(smem + SMB_H + oc*CPITCH + q*16) =
                *(const float4*)(wsrcH + (size_t)tap*8192 + oc*128 + q*16);
            *(float4*)(smem + SMB_L + oc*CPITCH + q*16) =
                *(const float4*)(wsrcL + (size_t)tap*8192 + oc*128 + q*16);
        }
        __syncthreads();

        #pragma unroll
        for (int k16 = 0; k16 < 4; ++k16) {
            const int kb = k16 * 32;
            uint32_t ah[2][4], al[2][4];
            #pragma unroll
            for (int m = 0; m < 2; m++) {
                const uint32_t apix = (uint32_t)(((h0_ + m + dy)*18 + wl + dx)*CPITCH + kh16 + kb);
                ldmx4(ah[m], sb + SM_CI_H + apix);
                ldmx4(al[m], sb + SM_CI_L + apix);
            }
            #pragma unroll
            for (int nt2 = 0; nt2 < 4; ++nt2) {
                uint32_t bh[4], bl[4];
                const uint32_t boff = (uint32_t)((nt2*16 + oc_l)*CPITCH + kb + koff);
                ldmx4(bh, sb + SMB_H + boff);
                ldmx4(bl, sb + SMB_L + boff);
                #pragma unroll
                for (int m = 0; m < 2; m++) {
                    mma16816(d[m][2*nt2],     ah[m], bh);
                    mma16816(d[m][2*nt2],     al[m], bh);
                    mma16816(d[m][2*nt2],     ah[m], bl);
                    mma16816(d[m][2*nt2 + 1], ah[m], bh + 2);
                    mma16816(d[m][2*nt2 + 1], al[m], bh + 2);
                    mma16816(d[m][2*nt2 + 1], ah[m], bl + 2);
                }
            }
        }
    }
    __syncthreads();   // all smem reads done; reuse ci region as D stage

    // scatter D frags to smem [oc][pos] pitch 1072
    {
        const int g  = lane >> 2;
        const int tg = lane & 3;
        #pragma unroll
        for (int m = 0; m < 2; m++) {
            const int hh = h0_ + m;
            const int pos0 = hh*16 + g;
            const int pos1 = pos0 + 8;
            #pragma unroll
            for (int n = 0; n < 8; n++) {
                char* base = smem + SM_DST + (n*8 + 2*tg)*DPITCH;
                *(float*)(base + pos0*4)          = d[m][n][0];
                *(float*)(base + DPITCH + pos0*4) = d[m][n][1];
                *(float*)(base + pos1*4)          = d[m][n][2];
                *(float*)(base + DPITCH + pos1*4) = d[m][n][3];
            }
        }
    }
    __syncthreads();

    float* dst = (mod == 0) ? g_h1 : (mod == 1) ? g_h2 : out_final;
    dst += (size_t)b * DIMC * HW;
    for (int i = tid; i < 4096; i += 256) {
        const int oc = i >> 6;
        const int p4 = (i & 63) * 4;
        float4 v = *(const float4*)(smem + SM_DST + oc*DPITCH + p4*4);
        const float bb = s_bias[oc];
        v.x = fmaxf(v.x + bb, 0.f);
        v.y = fmaxf(v.y + bb, 0.f);
        v.z = fmaxf(v.z + bb, 0.f);
        v.w = fmaxf(v.w + bb, 0.f);
        *(float4*)(dst + oc*256 + p4) = v;
    }
}

// =====================================================================
extern "C" void kernel_launch(void* const* d_in, const int* in_sizes, int n_in,
                              void* d_out, int out_size)
{
    const int*   question = (const int*)  d_in[0];
    const float* img      = (const float*)d_in[1];
    const float* emb      = (const float*)d_in[2];
    const float* alpha    = (const float*)d_in[3];
    const float* tau0     = (const float*)d_in[4];
    const float* tau1     = (const float*)d_in[5];
    float* out = (float*)d_out;

    cudaFuncSetAttribute(projm_kernel, cudaFuncAttributeMaxDynamicSharedMemorySize, PJ_TOT);
    cudaFuncSetAttribute(convm_kernel, cudaFuncAttributeMaxDynamicSharedMemorySize, SM_TOT);

    // all modules' conv + proj weights in one parallel launch
    wcomb_all_kernel<<<BATCH*15, 128>>>(question, emb, alpha);

    for (int mod = 0; mod < 3; ++mod) {
        projm_kernel<<<BATCH, 256, PJ_TOT>>>(question, img, emb, alpha, tau0, tau1, mod);
        convm_kernel<<<BATCH, 256, SM_TOT>>>(question, emb, alpha, out, mod);
    }
    (void)in_sizes; (void)n_in; (void)out_size;
}

// round 17
// speedup vs baseline: 1.1980x; 1.1191x over previous
#include <cuda_runtime.h>
#include <cuda_bf16.h>
#include <stdint.h>
#include <math.h>

// ---------------- problem constants ----------------
#define DIMC      64
#define HW        256          // 16x16
#define BATCH     256
#define EMB_DIM   45184
#define OFF_CNNW  0
#define OFF_CNNB  36864
#define OFF_PROJW 36928
#define OFF_PROJB 45120
#define BHW       (BATCH*DIMC*HW)   // 16 MB

typedef unsigned long long ull_t;

// scratch
__device__ float g_h1[BHW];
__device__ float g_h2[BHW];
// combined conv weights, per mod, tap-major, split bf16: [mod][b][tap][oc][cl]
__device__ __nv_bfloat16 g_wh[3*BATCH*9*64*64];
__device__ __nv_bfloat16 g_wl[3*BATCH*9*64*64];
// combined proj weights, split bf16: [mod][b][half][oc][k64]
__device__ __nv_bfloat16 g_pwh[3*BATCH*2*64*64];
__device__ __nv_bfloat16 g_pwl[3*BATCH*2*64*64];

__device__ __forceinline__ void softmax_n(const float* x, float* y, int n) {
    float m = x[0];
    for (int i = 1; i < n; i++) m = fmaxf(m, x[i]);
    float s = 0.f;
    for (int i = 0; i < n; i++) { y[i] = expf(x[i] - m); s += y[i]; }
    float inv = 1.f / s;
    for (int i = 0; i < n; i++) y[i] *= inv;
}

__device__ __forceinline__ uint32_t smem_to_u32(const void* p) {
    uint32_t a;
    asm("{ .reg .u64 t; cvta.to.shared.u64 t, %1; cvt.u32.u64 %0, t; }" : "=r"(a) : "l"(p));
    return a;
}

// ldmatrix x4 (sm_75+ baseline)
__device__ __forceinline__ void ldmx4(uint32_t* r, uint32_t addr) {
    asm volatile("ldmatrix.sync.aligned.m8n8.x4.shared.b16 {%0,%1,%2,%3}, [%4];"
        : "=r"(r[0]), "=r"(r[1]), "=r"(r[2]), "=r"(r[3]) : "r"(addr));
}
// bf16 HMMA (sm_80+ baseline)
__device__ __forceinline__ void mma16816(float* d, const uint32_t* a, const uint32_t* b) {
    asm volatile("mma.sync.aligned.m16n8k16.row.col.f32.bf16.bf16.f32 "
        "{%0,%1,%2,%3}, {%4,%5,%6,%7}, {%8,%9}, {%0,%1,%2,%3};"
        : "+f"(d[0]), "+f"(d[1]), "+f"(d[2]), "+f"(d[3])
        : "r"(a[0]), "r"(a[1]), "r"(a[2]), "r"(a[3]), "r"(b[0]), "r"(b[1]));
}

__device__ __forceinline__ __nv_bfloat162 split_hi2(float x, float y) {
    __nv_bfloat162 r; r.x = __float2bfloat16(x); r.y = __float2bfloat16(y); return r;
}
__device__ __forceinline__ __nv_bfloat162 split_lo2(float x, float y,
                                                    __nv_bfloat162 h) {
    __nv_bfloat162 r;
    r.x = __float2bfloat16(x - __bfloat162float(h.x));
    r.y = __float2bfloat16(y - __bfloat162float(h.y));
    return r;
}

// =====================================================================
// Kernel W: combine conv + proj weights for ALL modules, one launch.
// grid 3840 = 256 b x 3 mod x (4 conv oc-chunks + 1 proj chunk), 128 thr.
// =====================================================================
__global__ void __launch_bounds__(128)
wcomb_all_kernel(const int* __restrict__ question,
                 const float* __restrict__ emb,
                 const float* __restrict__ alpha)
{
    __shared__ float ws[16*580];
    __shared__ float s_a[3];
    const int idx   = blockIdx.x;
    const int b     = idx / 15;
    const int r     = idx % 15;
    const int mod   = r / 5;
    const int sub   = r % 5;
    const int tid   = threadIdx.x;

    if (tid == 0) {
        float tmp[3], sf[3];
        for (int t = 0; t < 3; t++) tmp[t] = alpha[mod*3 + t];
        softmax_n(tmp, sf, 3);
        s_a[0] = sf[0]; s_a[1] = sf[1]; s_a[2] = sf[2];
    }
    __syncthreads();
    const float a0 = s_a[0], a1 = s_a[1], a2 = s_a[2];
    const float* r0 = emb + (size_t)question[b*3 + 0] * EMB_DIM;
    const float* r1 = emb + (size_t)question[b*3 + 1] * EMB_DIM;
    const float* r2 = emb + (size_t)question[b*3 + 2] * EMB_DIM;

    if (sub == 4) {
        // proj weights: [half][oc][k64] bf16 split
        const size_t pbase = ((size_t)mod*BATCH + b) * 2*64*64;
        for (int i4 = tid; i4 < 2048; i4 += 128) {
            const int oc = i4 >> 5;
            const int k4 = (i4 & 31) * 4;
            const int f  = OFF_PROJW + oc*128 + k4;
            float4 x = *(const float4*)(r0 + f);
            float4 y = *(const float4*)(r1 + f);
            float4 z = *(const float4*)(r2 + f);
            float4 o;
            o.x = a0*x.x + a1*y.x + a2*z.x;
            o.y = a0*x.y + a1*y.y + a2*z.y;
            o.z = a0*x.z + a1*y.z + a2*z.z;
            o.w = a0*x.w + a1*y.w + a2*z.w;
            const int half = k4 >> 6;
            const int kk   = k4 & 63;
            __nv_bfloat162 hp0 = split_hi2(o.x, o.y);
            __nv_bfloat162 lp0 = split_lo2(o.x, o.y, hp0);
            __nv_bfloat162 hp1 = split_hi2(o.z, o.w);
            __nv_bfloat162 lp1 = split_lo2(o.z, o.w, hp1);
            const size_t gi = pbase + (size_t)half*4096 + oc*64 + kk;
            *(__nv_bfloat162*)&g_pwh[gi]     = hp0;
            *(__nv_bfloat162*)&g_pwh[gi + 2] = hp1;
            *(__nv_bfloat162*)&g_pwl[gi]     = lp0;
            *(__nv_bfloat162*)&g_pwl[gi + 2] = lp1;
        }
        return;
    }

    const int chunk = sub;
    const size_t obase = ((size_t)mod*BATCH + b) * 9 * 4096;
    const int oc0 = chunk * 16;

    for (int i4 = tid; i4 < 16*144; i4 += 128) {
        const int oc_l = i4 / 144;
        const int c4   = i4 % 144;
        const int f = (oc0 + oc_l)*576 + c4*4;
        float4 x = *(const float4*)(r0 + f);
        float4 y = *(const float4*)(r1 + f);
        float4 z = *(const float4*)(r2 + f);
        float4 o;
        o.x = a0*x.x + a1*y.x + a2*z.x;
        o.y = a0*x.y + a1*y.y + a2*z.y;
        o.z = a0*x.z + a1*y.z + a2*z.z;
        o.w = a0*x.w + a1*y.w + a2*z.w;
        *(float4*)&ws[oc_l*580 + c4*4] = o;
    }
    __syncthreads();
    for (int tap = 0; tap < 9; ++tap) {
        for (int e2 = tid; e2 < 512; e2 += 128) {
            const int oc_l = e2 >> 5;
            const int cl   = (e2 & 31) * 2;
            const float w0 = ws[oc_l*580 + cl*9 + tap];
            const float w1 = ws[oc_l*580 + (cl + 1)*9 + tap];
            __nv_bfloat162 hp = split_hi2(w0, w1);
            __nv_bfloat162 lp = split_lo2(w0, w1, hp);
            const size_t gi = obase + (size_t)tap*4096 + (oc0 + oc_l)*64 + cl;
            *(__nv_bfloat162*)&g_wh[gi] = hp;
            *(__nv_bfloat162*)&g_wl[gi] = lp;
        }
    }
}

// =====================================================================
// Kernel F (fused proj + conv, HMMA): one CTA per batch element.
// grid 256, 256 thr (8 warps), 2 CTAs/SM.
// Phase 1 (proj): D[256 pos, 64 ch] = inp[256,128] @ W^T + pb, 2 K-halves;
//   A staged in the CI smem region (disjoint lifetime), B = row copy.
// Phase 2: halo-zero + scatter proj frags (split hi/lo) directly into the
//   padded conv CI layout in smem — NO gmem ci roundtrip.
// Phase 3 (conv): 9-tap HMMA as before; epilogue bias+ReLU -> h / out.
// =====================================================================
#define CPITCH 144
#define F_BH    0                         // 64*144 = 9216 (proj B / conv B hi)
#define F_BL    9216                      // (lo) -> 18432
#define F_BIAS  18432                     // conv bias 64 f -> 18688
#define F_PB    18688                     // proj bias 64 f -> 18944
#define F_SCAL  18944                     // 9 scalars (pad) -> 19072
#define F_CI    19072                     // 93312-byte region
#define F_AH    (F_CI)                    // proj A hi (36864)
#define F_AL    (F_CI + 36864)            // proj A lo (36864)
#define F_CIH   (F_CI)                    // conv ci hi (46656)
#define F_CIL   (F_CI + 46656)            // conv ci lo (46656)
#define F_DST   (F_CI)                    // D stage reuse (68608)
#define DPITCH  1072
#define F_TOT   (F_CI + 93312)            // 112384 bytes

__global__ void __launch_bounds__(256, 2)
fused_kernel(const int* __restrict__ question,
             const float* __restrict__ img,
             const float* __restrict__ emb,
             const float* __restrict__ alpha,
             const float* __restrict__ tau0,
             const float* __restrict__ tau1,
             float* __restrict__ out_final,
             int mod)
{
    extern __shared__ char smem[];
    const uint32_t sb = smem_to_u32(smem);
    const int b    = blockIdx.x;
    const int tid  = threadIdx.x;
    const int warp = tid >> 5;
    const int lane = tid & 31;
    float* s_bias = (float*)(smem + F_BIAS);
    float* s_pb   = (float*)(smem + F_PB);
    float* s_scal = (float*)(smem + F_SCAL);

    if (tid == 0) {
        float tmp[4], sf[4];
        for (int t = 0; t < 3; t++) tmp[t] = alpha[mod*3 + t];
        softmax_n(tmp, sf, 3);
        s_scal[0] = sf[0]; s_scal[1] = sf[1]; s_scal[2] = sf[2];
        const int n = mod + 2;
        for (int m = 0; m < n; m++) tmp[m] = tau0[mod*4 + m];
        softmax_n(tmp, sf, n);
        s_scal[3] = sf[1];
        s_scal[4] = (n > 2) ? sf[2] : 0.f;
        s_scal[5] = (n > 3) ? sf[3] : 0.f;
        for (int m = 0; m < n; m++) tmp[m] = tau1[mod*4 + m];
        softmax_n(tmp, sf, n);
        s_scal[6] = sf[1];
        s_scal[7] = (n > 2) ? sf[2] : 0.f;
        s_scal[8] = (n > 3) ? sf[3] : 0.f;
    }
    __syncthreads();

    const float a0 = s_scal[0], a1 = s_scal[1], a2 = s_scal[2];
    const float* r0 = emb + (size_t)question[b*3 + 0] * EMB_DIM;
    const float* r1 = emb + (size_t)question[b*3 + 1] * EMB_DIM;
    const float* r2 = emb + (size_t)question[b*3 + 2] * EMB_DIM;
    if (tid < 64)
        s_pb[tid] = a0*r0[OFF_PROJB + tid] + a1*r1[OFF_PROJB + tid] + a2*r2[OFF_PROJB + tid];
    else if (tid < 128) {
        const int o = tid - 64;
        s_bias[o] = a0*r0[OFF_CNNB + o] + a1*r1[OFF_CNNB + o] + a2*r2[OFF_CNNB + o];
    }

    // lane-dependent fragment address pieces (shared by both phases)
    const int wl   = lane & 15;
    const int kh16 = (lane >> 4) * 16;
    const int oc_l = ((lane >> 4) & 1)*8 + (lane & 7);
    const int koff = ((lane >> 3) & 1) * 16;
    const int g    = lane >> 2;
    const int tg   = lane & 3;

    const float4* img4 = (const float4*)(img  + (size_t)b * DIMC * HW);
    const float4* h14  = (const float4*)(g_h1 + (size_t)b * DIMC * HW);
    const float4* h24  = (const float4*)(g_h2 + (size_t)b * DIMC * HW);
    const char* pwh = (const char*)(g_pwh + ((size_t)mod*BATCH + b) * 2*64*64);
    const char* pwl = (const char*)(g_pwl + ((size_t)mod*BATCH + b) * 2*64*64);

    // ---------------- Phase 1: projection ----------------
    float d[2][8][4];
    __syncthreads();   // s_pb ready
    #pragma unroll
    for (int n = 0; n < 8; n++) {
        const float p0 = s_pb[n*8 + 2*tg];
        const float p1 = s_pb[n*8 + 2*tg + 1];
        #pragma unroll
        for (int m = 0; m < 2; m++) {
            d[m][n][0] = p0; d[m][n][1] = p1;
            d[m][n][2] = p0; d[m][n][3] = p1;
        }
    }

    for (int half = 0; half < 2; ++half) {
        const float w1 = s_scal[3 + 3*half + 0];
        const float w2 = s_scal[3 + 3*half + 1];
        const float w3 = s_scal[3 + 3*half + 2];
        __syncthreads();   // prev half's smem reads done

        // A stage: inp-half [pos 256][ch 64] bf16 hi/lo, pitch 144
        for (int ii = tid; ii < 2048; ii += 256) {
            const int cp = ii >> 6;
            const int q  = ii & 63;
            const int i0 = (2*cp)*64 + q;
            float4 u0 = img4[i0];
            float4 u1 = img4[i0 + 64];
            float4 o0, o1;
            o0.x = w1*u0.x; o0.y = w1*u0.y; o0.z = w1*u0.z; o0.w = w1*u0.w;
            o1.x = w1*u1.x; o1.y = w1*u1.y; o1.z = w1*u1.z; o1.w = w1*u1.w;
            if (mod >= 1) {
                float4 v0 = h14[i0], v1 = h14[i0 + 64];
                o0.x += w2*v0.x; o0.y += w2*v0.y; o0.z += w2*v0.z; o0.w += w2*v0.w;
                o1.x += w2*v1.x; o1.y += w2*v1.y; o1.z += w2*v1.z; o1.w += w2*v1.w;
            }
            if (mod >= 2) {
                float4 v0 = h24[i0], v1 = h24[i0 + 64];
                o0.x += w3*v0.x; o0.y += w3*v0.y; o0.z += w3*v0.z; o0.w += w3*v0.w;
                o1.x += w3*v1.x; o1.y += w3*v1.y; o1.z += w3*v1.z; o1.w += w3*v1.w;
            }
            const float x0[4] = { o0.x, o0.y, o0.z, o0.w };
            const float x1[4] = { o1.x, o1.y, o1.z, o1.w };
            const int p0 = q * 4;
            #pragma unroll
            for (int l = 0; l < 4; l++) {
                __nv_bfloat162 hp = split_hi2(x0[l], x1[l]);
                __nv_bfloat162 lp = split_lo2(x0[l], x1[l], hp);
                *(__nv_bfloat162*)(smem + F_AH + (p0 + l)*CPITCH + cp*4) = hp;
                *(__nv_bfloat162*)(smem + F_AL + (p0 + l)*CPITCH + cp*4) = lp;
            }
        }
        // B stage: pure 128B row copy from precomputed weights
        for (int i = tid; i < 512; i += 256) {
            const int oc = i >> 3;
            const int q  = i & 7;
            *(float4*)(smem + F_BH + oc*CPITCH + q*16) =
                *(const float4*)(pwh + (size_t)half*8192 + oc*128 + q*16);
            *(float4*)(smem + F_BL + oc*CPITCH + q*16) =
                *(const float4*)(pwl + (size_t)half*8192 + oc*128 + q*16);
        }
        __syncthreads();

        #pragma unroll
        for (int k16 = 0; k16 < 4; ++k16) {
            const int kb = k16 * 32;
            uint32_t ah[2][4], al[2][4];
            #pragma unroll
            for (int m = 0; m < 2; m++) {
                const uint32_t apix = (uint32_t)((warp*32 + m*16 + wl)*CPITCH + kh16 + kb);
                ldmx4(ah[m], sb + F_AH + apix);
                ldmx4(al[m], sb + F_AL + apix);
            }
            #pragma unroll
            for (int nt2 = 0; nt2 < 4; ++nt2) {
                uint32_t bh[4], bl[4];
                const uint32_t boff = (uint32_t)((nt2*16 + oc_l)*CPITCH + kb + koff);
                ldmx4(bh, sb + F_BH + boff);
                ldmx4(bl, sb + F_BL + boff);
                #pragma unroll
                for (int m = 0; m < 2; m++) {
                    mma16816(d[m][2*nt2],     ah[m], bh);
                    mma16816(d[m][2*nt2],     al[m], bh);
                    mma16816(d[m][2*nt2],     ah[m], bl);
                    mma16816(d[m][2*nt2 + 1], ah[m], bh + 2);
                    mma16816(d[m][2*nt2 + 1], al[m], bh + 2);
                    mma16816(d[m][2*nt2 + 1], ah[m], bl + 2);
                }
            }
        }
    }
    __syncthreads();   // all proj smem reads done — CI region reusable

    // ---------------- Phase 2: halo-zero + scatter to conv CI ----------------
    // zero the 68 halo pixels (rows 0/17, cols 0/17), hi and lo
    for (int e = tid; e < 68*18; e += 256) {
        const int hp = e / 18;
        const int q  = e % 18;
        int pix;
        if (hp < 18)       pix = hp;                 // row 0
        else if (hp < 36)  pix = 306 + (hp - 18);    // row 17
        else {
            const int j = hp - 36;                   // 16 rows x 2 cols
            pix = (1 + (j >> 1))*18 + ((j & 1) ? 17 : 0);
        }
        char* base = (q < 9) ? (smem + F_CIH + pix*CPITCH + q*16)
                             : (smem + F_CIL + pix*CPITCH + (q - 9)*16);
        *(float4*)base = make_float4(0.f, 0.f, 0.f, 0.f);
    }
    // scatter proj D frags (split hi/lo) into padded CI interior
    #pragma unroll
    for (int m = 0; m < 2; m++) {
        const int row0 = warp*32 + m*16 + g;
        const int row1 = row0 + 8;
        const int pix0 = ((row0 >> 4) + 1)*18 + ((row0 & 15) + 1);
        const int pix1 = ((row1 >> 4) + 1)*18 + ((row1 & 15) + 1);
        #pragma unroll
        for (int n = 0; n < 8; n++) {
            const int col = n*8 + 2*tg;
            __nv_bfloat162 h0 = split_hi2(d[m][n][0], d[m][n][1]);
            __nv_bfloat162 l0 = split_lo2(d[m][n][0], d[m][n][1], h0);
            __nv_bfloat162 h1 = split_hi2(d[m][n][2], d[m][n][3]);
            __nv_bfloat162 l1 = split_lo2(d[m][n][2], d[m][n][3], h1);
            *(__nv_bfloat162*)(smem + F_CIH + pix0*CPITCH + col*2) = h0;
            *(__nv_bfloat162*)(smem + F_CIL + pix0*CPITCH + col*2) = l0;
            *(__nv_bfloat162*)(smem + F_CIH + pix1*CPITCH + col*2) = h1;
            *(__nv_bfloat162*)(smem + F_CIL + pix1*CPITCH + col*2) = l1;
        }
    }
    __syncthreads();

    // ---------------- Phase 3: conv ----------------
    #pragma unroll
    for (int m = 0; m < 2; m++)
        #pragma unroll
        for (int n = 0; n < 8; n++)
            #pragma unroll
            for (int q = 0; q < 4; q++) d[m][n][q] = 0.f;

    const int h0_ = warp*2;
    const char* wsrcH = (const char*)(g_wh + ((size_t)mod*BATCH + b)*9*4096);
    const char* wsrcL = (const char*)(g_wl + ((size_t)mod*BATCH + b)*9*4096);

    for (int tap = 0; tap < 9; ++tap) {
        const int dy = tap / 3;
        const int dx = tap % 3;
        __syncthreads();     // prev-tap B reads done
        for (int i = tid; i < 512; i += 256) {
            const int oc = i >> 3;
            const int q  = i & 7;
            *(float4*)(smem + F_BH + oc*CPITCH + q*16) =
                *(const float4*)(wsrcH + (size_t)tap*8192 + oc*128 + q*16);
            *(float4*)(smem + F_BL + oc*CPITCH + q*16) =
                *(const float4*)(wsrcL + (size_t)tap*8192 + oc*128 + q*16);
        }
        __syncthreads();

        #pragma unroll
        for (int k16 = 0; k16 < 4; ++k16) {
            const int kb = k16 * 32;
            uint32_t ah[2][4], al[2][4];
            #pragma unroll
            for (int m = 0; m < 2; m++) {
                const uint32_t apix = (uint32_t)(((h0_ + m + dy)*18 + wl + dx)*CPITCH + kh16 + kb);
                ldmx4(ah[m], sb + F_CIH + apix);
                ldmx4(al[m], sb + F_CIL + apix);
            }
            #pragma unroll
            for (int nt2 = 0; nt2 < 4; ++nt2) {
                uint32_t bh[4], bl[4];
                const uint32_t boff = (uint32_t)((nt2*16 + oc_l)*CPITCH + kb + koff);
                ldmx4(bh, sb + F_BH + boff);
                ldmx4(bl, sb + F_BL + boff);
                #pragma unroll
                for (int m = 0; m < 2; m++) {
                    mma16816(d[m][2*nt2],     ah[m], bh);
                    mma16816(d[m][2*nt2],     al[m], bh);
                    mma16816(d[m][2*nt2],     ah[m], bl);
                    mma16816(d[m][2*nt2 + 1], ah[m], bh + 2);
                    mma16816(d[m][2*nt2 + 1], al[m], bh + 2);
                    mma16816(d[m][2*nt2 + 1], ah[m], bl + 2);
                }
            }
        }
    }
    __syncthreads();   // all conv smem reads done; reuse CI region as D stage

    // scatter D frags to smem [oc][pos] pitch 1072
    #pragma unroll
    for (int m = 0; m < 2; m++) {
        const int hh = h0_ + m;
        const int pos0 = hh*16 + g;
        const int pos1 = pos0 + 8;
        #pragma unroll
        for (int n = 0; n < 8; n++) {
            char* base = smem + F_DST + (n*8 + 2*tg)*DPITCH;
            *(float*)(base + pos0*4)          = d[m][n][0];
            *(float*)(base + DPITCH + pos0*4) = d[m][n][1];
            *(float*)(base + pos1*4)          = d[m][n][2];
            *(float*)(base + DPITCH + pos1*4) = d[m][n][3];
        }
    }
    __syncthreads();

    float* dst = (mod == 0) ? g_h1 : (mod == 1) ? g_h2 : out_final;
    dst += (size_t)b * DIMC * HW;
    for (int i = tid; i < 4096; i += 256) {
        const int oc = i >> 6;
        const int p4 = (i & 63) * 4;
        float4 v = *(const float4*)(smem + F_DST + oc*DPITCH + p4*4);
        const float bb = s_bias[oc];
        v.x = fmaxf(v.x + bb, 0.f);
        v.y = fmaxf(v.y + bb, 0.f);
        v.z = fmaxf(v.z + bb, 0.f);
        v.w = fmaxf(v.w + bb, 0.f);
        *(float4*)(dst + oc*256 + p4) = v;
    }
}

// =====================================================================
extern "C" void kernel_launch(void* const* d_in, const int* in_sizes, int n_in,
                              void* d_out, int out_size)
{
    const int*   question = (const int*)  d_in[0];
    const float* img      = (const float*)d_in[1];
    const float* emb      = (const float*)d_in[2];
    const float* alpha    = (const float*)d_in[3];
    const float* tau0     = (const float*)d_in[4];
    const float* tau1     = (const float*)d_in[5];
    float* out = (float*)d_out;

    cudaFuncSetAttribute(fused_kernel, cudaFuncAttributeMaxDynamicSharedMemorySize, F_TOT);

    // all modules' conv + proj weights in one parallel launch
    wcomb_all_kernel<<<BATCH*15, 128>>>(question, emb, alpha);

    for (int mod = 0; mod < 3; ++mod)
        fused_kernel<<<BATCH, 256, F_TOT>>>(question, img, emb, alpha, tau0, tau1, out, mod);

    (void)in_sizes; (void)n_in; (void)out_size;
}